// round 4
// baseline (speedup 1.0000x reference)
#include <cuda_runtime.h>
#include <cstdint>

// Problem constants
#define BB   4
#define TT   2048
#define HID  2048
#define NH   16
#define HD   128
#define MTOT (BB * TT)          // 8192
#define KDIM 2048

// Scratch (device globals; allocation-free rule)
__device__ float g_x    [(size_t)MTOT * KDIM];        // tf32-rounded x
__device__ float g_wqkv [(size_t)3 * HID * KDIM];     // tf32-rounded w_qkv
__device__ float g_wproj[(size_t)HID * KDIM];         // tf32-rounded w_proj
__device__ float g_Q [(size_t)BB * NH * TT * HD];
__device__ float g_K [(size_t)BB * NH * TT * HD];
__device__ float g_Vt[(size_t)BB * NH * HD * TT];     // V^T: [bh][d][t]
__device__ float g_attn[(size_t)MTOT * HID];          // tf32-rounded attn out

// ---------------------------------------------------------------------------
// helpers
// ---------------------------------------------------------------------------
__device__ __forceinline__ float f2tff(float x) {
    uint32_t r;
    asm("cvt.rna.tf32.f32 %0, %1;" : "=r"(r) : "f"(x));
    return __uint_as_float(r);
}
__device__ __forceinline__ void mma8(float* c, const uint32_t* a, const uint32_t* b) {
    asm volatile(
        "mma.sync.aligned.m16n8k8.row.col.f32.tf32.tf32.f32 "
        "{%0,%1,%2,%3},{%4,%5,%6,%7},{%8,%9},{%0,%1,%2,%3};\n"
        : "+f"(c[0]), "+f"(c[1]), "+f"(c[2]), "+f"(c[3])
        : "r"(a[0]), "r"(a[1]), "r"(a[2]), "r"(a[3]), "r"(b[0]), "r"(b[1]));
}
__device__ __forceinline__ uint32_t smem_u32(const void* p) {
    return (uint32_t)__cvta_generic_to_shared(p);
}
#define CP16(dst_u32, src_ptr) \
    asm volatile("cp.async.cg.shared.global [%0], [%1], 16;\n" :: "r"(dst_u32), "l"(src_ptr))
#define CP_COMMIT() asm volatile("cp.async.commit_group;\n" ::)
#define CP_WAIT1()  asm volatile("cp.async.wait_group 1;\n" ::)

// ---------------------------------------------------------------------------
// pre-round inputs to tf32
// ---------------------------------------------------------------------------
template <int WHICH>
__global__ void round_kernel(const float* __restrict__ src, int n)
{
    float* dst = (WHICH == 0) ? g_x : (WHICH == 1) ? g_wqkv : g_wproj;
    int stride = gridDim.x * blockDim.x * 4;
    for (int i = (blockIdx.x * blockDim.x + threadIdx.x) * 4; i < n; i += stride) {
        float4 v = *(const float4*)(src + i);
        *(float4*)(dst + i) = make_float4(f2tff(v.x), f2tff(v.y), f2tff(v.z), f2tff(v.w));
    }
}

// ---------------------------------------------------------------------------
// GEMM: C[M,N] = A[M,K] * Bw[N,K]^T  via m16n8k8 tf32 mma.
// Block tile 128(M) x 256(N) x 32(K). 256 thr = 8 warps (2m x 4n), warp 64x64.
// cp.async 3-stage pipeline, ONE __syncthreads per k-iter (issue after sync).
// smem rows: 32 floats, 8 f4 chunks, chunk col' = c4 ^ (row & 7).
// MODE 0: A=g_x, Bw=g_wqkv; epilogue RoPE+qscale, scatter Q/K (V transposed).
// MODE 1: A=g_attn, Bw=g_wproj; epilogue + bias -> Cout.
// ---------------------------------------------------------------------------
#define GSTAGES 3
#define GEMM_SMEM (GSTAGES * (128 + 256) * 32 * 4)   // 147456 bytes

template <int MODE>
__global__ __launch_bounds__(256, 1)
void gemm_kernel(const float* __restrict__ cosT,
                 const float* __restrict__ sinT,
                 const float* __restrict__ bias,
                 float* __restrict__ Cout)
{
    extern __shared__ float sm[];
    float* As = sm;                          // GSTAGES * 128*32
    float* Bs = sm + GSTAGES * 4096;         // GSTAGES * 256*32

    const int tid  = threadIdx.x;
    const int lane = tid & 31;
    const int w    = tid >> 5;
    const int gy   = lane >> 2;   // 0..7
    const int gx   = lane & 3;    // 0..3
    const int wm   = (w & 1) * 64;
    const int wn   = (w >> 1) * 64;
    const long row0 = (long)blockIdx.x * 128;
    const long col0 = (long)blockIdx.y * 256;

    const float* __restrict__ Ap = (MODE == 0) ? g_x    : g_attn;
    const float* __restrict__ Bp = (MODE == 0) ? g_wqkv : g_wproj;

    // load maps
    int arow[4], ac4[4], aoff[4];
#pragma unroll
    for (int j = 0; j < 4; j++) {
        int f = tid + j * 256;
        arow[j] = f >> 3;  ac4[j] = f & 7;
        aoff[j] = (arow[j] * 32 + ((ac4[j] ^ (arow[j] & 7)) * 4)) * 4;
    }
    int brow[8], bc4[8], boff[8];
#pragma unroll
    for (int j = 0; j < 8; j++) {
        int f = tid + j * 256;
        brow[j] = f >> 3;  bc4[j] = f & 7;
        boff[j] = (brow[j] * 32 + ((bc4[j] ^ (brow[j] & 7)) * 4)) * 4;
    }
    const uint32_t sA = smem_u32(As);
    const uint32_t sB = smem_u32(Bs);

    auto issue = [&](int kb, int slot) {
        if (kb < KDIM) {
            const uint32_t ba = sA + slot * 16384;    // 4096 floats
            const uint32_t bb = sB + slot * 32768;    // 8192 floats
#pragma unroll
            for (int j = 0; j < 4; j++)
                CP16(ba + aoff[j], Ap + (row0 + arow[j]) * KDIM + kb + ac4[j] * 4);
#pragma unroll
            for (int j = 0; j < 8; j++)
                CP16(bb + boff[j], Bp + (col0 + brow[j]) * KDIM + kb + bc4[j] * 4);
        }
        CP_COMMIT();
    };

    float acc[4][8][4];
#pragma unroll
    for (int s = 0; s < 4; s++)
#pragma unroll
        for (int t = 0; t < 8; t++)
#pragma unroll
            for (int j = 0; j < 4; j++) acc[s][t][j] = 0.0f;

    issue(0, 0);
    issue(32, 1);

    for (int it = 0; it < KDIM / 32; it++) {
        CP_WAIT1();
        __syncthreads();
        issue((it + 2) * 32, (it + 2) % GSTAGES);

        const float* Sa = As + (it % GSTAGES) * 4096;
        const float* Sb = Bs + (it % GSTAGES) * 8192;
#pragma unroll
        for (int ks = 0; ks < 4; ks++) {
            const int i0 = ((2 * ks)     ^ gy) * 4 + gx;
            const int i1 = ((2 * ks + 1) ^ gy) * 4 + gx;
            uint32_t af[4][4], bf[8][2];
#pragma unroll
            for (int s = 0; s < 4; s++) {
                const float* p = Sa + (wm + 16 * s + gy) * 32;
                af[s][0] = __float_as_uint(p[i0]);
                af[s][1] = __float_as_uint(p[i0 + 256]);
                af[s][2] = __float_as_uint(p[i1]);
                af[s][3] = __float_as_uint(p[i1 + 256]);
            }
#pragma unroll
            for (int t = 0; t < 8; t++) {
                const float* p = Sb + (wn + 8 * t + gy) * 32;
                bf[t][0] = __float_as_uint(p[i0]);
                bf[t][1] = __float_as_uint(p[i1]);
            }
#pragma unroll
            for (int s = 0; s < 4; s++)
#pragma unroll
                for (int t = 0; t < 8; t++)
                    mma8(acc[s][t], af[s], bf[t]);
        }
    }
    // NOTE: last two issue() calls are empty commits (kb >= KDIM), pipeline drains.

    // Epilogue. rows: row0+wm+16s+gy+8h; cols: col0+wn+8t+2gx(+1).
    if (MODE == 0) {
        const float qscale = 0.08838834764831845f;   // 1/sqrt(128)
#pragma unroll
        for (int t = 0; t < 8; t++) {
            const int noff = wn + 8 * t + 2 * gx;     // 0..254 within 256-tile
            const long n   = col0 + noff;
            const int sec  = (int)(n >> 11);          // 0=Q 1=K 2=V
            const int head = ((int)n >> 7) & 15;
            const int d    = (int)n & 127;
            const int p    = d >> 1;
#pragma unroll
            for (int s = 0; s < 4; s++)
#pragma unroll
                for (int h = 0; h < 2; h++) {
                    long r = row0 + wm + 16 * s + gy + 8 * h;
                    int  b  = (int)(r >> 11);
                    int  tt = (int)r & 2047;
                    float v0 = acc[s][t][2 * h + 0];
                    float v1 = acc[s][t][2 * h + 1];
                    if (sec < 2) {
                        float c  = cosT[tt * 64 + p];
                        float sn = sinT[tt * 64 + p];
                        float e = v0, o = v1;
                        v0 = e * c - o * sn;
                        v1 = e * sn + o * c;
                        if (sec == 0) { v0 *= qscale; v1 *= qscale; }
                    }
                    v0 = f2tff(v0); v1 = f2tff(v1);
                    long bh = (long)b * NH + head;
                    if (sec == 2) {
                        g_Vt[(bh * HD + d)     * TT + tt] = v0;
                        g_Vt[(bh * HD + d + 1) * TT + tt] = v1;
                    } else {
                        float* dst = (sec == 0) ? g_Q : g_K;
                        *(float2*)&dst[(bh * TT + tt) * HD + d] = make_float2(v0, v1);
                    }
                }
        }
    } else {
#pragma unroll
        for (int t = 0; t < 8; t++) {
            const long n = col0 + wn + 8 * t + 2 * gx;
            float2 bv = *(const float2*)&bias[n];
#pragma unroll
            for (int s = 0; s < 4; s++)
#pragma unroll
                for (int h = 0; h < 2; h++) {
                    long r = row0 + wm + 16 * s + gy + 8 * h;
                    *(float2*)&Cout[r * HID + n] =
                        make_float2(acc[s][t][2 * h] + bv.x, acc[s][t][2 * h + 1] + bv.y);
                }
        }
    }
}

// ---------------------------------------------------------------------------
// Flash attention via tf32 mma.
// One block per (bh, 128-row q tile). KV tiles of 32. 8 warps, each 16 q rows.
// Q fragments live in REGISTERS (loaded once via smem staging).
// K/V: 3-stage cp.async pipeline, ONE __syncthreads per iter.
// smem floats: K 3*4096, V 3*4096, P 128*36 -> 29184 (116736 B).
// ---------------------------------------------------------------------------
#define QT  128
#define KVT 32
#define LPV 36
#define ATTN_SMEM ((3 * 4096 * 2 + QT * LPV) * 4)

__global__ __launch_bounds__(256, 1)
void attn_kernel()
{
    extern __shared__ float sm[];
    float* Kst = sm;                  // 3 * 32*128
    float* Vst = Kst + 3 * 4096;      // 3 * 128*32
    float* Ps  = Vst + 3 * 4096;      // 128*36

    const int tid  = threadIdx.x;
    const int lane = tid & 31;
    const int w    = tid >> 5;
    const int gy   = lane >> 2;
    const int gx   = lane & 3;
    const int bh   = blockIdx.y;
    const int q0   = blockIdx.x * QT;
    const int qw   = w * 16;

    const float* __restrict__ Qg = g_Q  + (long)bh * TT * HD;
    const float* __restrict__ Kg = g_K  + (long)bh * TT * HD;
    const float* __restrict__ Vg = g_Vt + (long)bh * HD * TT;

    const uint32_t sK = smem_u32(Kst);
    const uint32_t sV = smem_u32(Vst);

    // ---- Stage Q through smem (Kst area), pull fragments into registers ----
    uint32_t q[16][4];
    {
        float* Qtmp = Kst;   // 16384 floats needed; Kst+Vst = 24576 available
#pragma unroll
        for (int i = 0; i < 16; i++) {
            int f = tid + i * 256;
            int r = f >> 5, c4 = f & 31;
            int cs = (c4 & 24) | ((c4 & 7) ^ (r & 7));
            *(float4*)&Qtmp[r * 128 + cs * 4] =
                *(const float4*)&Qg[(long)(q0 + r) * HD + c4 * 4];
        }
        __syncthreads();
        const float* qp = Qtmp + (qw + gy) * 128;
#pragma unroll
        for (int ks = 0; ks < 16; ks++) {
            const int c0 = 2 * ks, c1 = 2 * ks + 1;
            const int i0 = ((c0 & 24) | ((c0 & 7) ^ gy)) * 4 + gx;
            const int i1 = ((c1 & 24) | ((c1 & 7) ^ gy)) * 4 + gx;
            q[ks][0] = __float_as_uint(qp[i0]);
            q[ks][1] = __float_as_uint(qp[i0 + 1024]);
            q[ks][2] = __float_as_uint(qp[i1]);
            q[ks][3] = __float_as_uint(qp[i1 + 1024]);
        }
        __syncthreads();
    }

    auto issueKV = [&](int kv0, int slot) {
        if (kv0 < TT) {
#pragma unroll
            for (int i = 0; i < 4; i++) {
                int f = tid + i * 256;
                int r = f >> 5, c4 = f & 31;
                int cs = (c4 & 24) | ((c4 & 7) ^ (r & 7));
                CP16(sK + (slot * 4096 + r * 128 + cs * 4) * 4,
                     Kg + (long)(kv0 + r) * HD + c4 * 4);
            }
#pragma unroll
            for (int i = 0; i < 4; i++) {
                int f = tid + i * 256;
                int d = f >> 3, k4 = f & 7;
                CP16(sV + (slot * 4096 + d * 32 + ((k4 ^ (d & 7)) * 4)) * 4,
                     Vg + (long)d * TT + kv0 + k4 * 4);
            }
        }
        CP_COMMIT();
    };

    float o[16][4];
#pragma unroll
    for (int dt = 0; dt < 16; dt++)
#pragma unroll
        for (int j = 0; j < 4; j++) o[dt][j] = 0.0f;
    float m0 = -3.0e38f, m1 = -3.0e38f, l0 = 0.0f, l1 = 0.0f;

    issueKV(0, 0);
    issueKV(KVT, 1);

    for (int i = 0; i < TT / KVT; i++) {
        CP_WAIT1();
        __syncthreads();
        issueKV((i + 2) * KVT, (i + 2) % 3);

        const float* Ks = Kst + (i % 3) * 4096;
        const float* Vs = Vst + (i % 3) * 4096;

        // S = Q . K^T : warp tile 16 x 32, k = 128 (A = registers)
        float s4[4][4];
#pragma unroll
        for (int t = 0; t < 4; t++)
#pragma unroll
            for (int j = 0; j < 4; j++) s4[t][j] = 0.0f;

#pragma unroll
        for (int ks = 0; ks < 16; ks++) {
            const int c0 = 2 * ks, c1 = 2 * ks + 1;
            const int i0 = ((c0 & 24) | ((c0 & 7) ^ gy)) * 4 + gx;
            const int i1 = ((c1 & 24) | ((c1 & 7) ^ gy)) * 4 + gx;
#pragma unroll
            for (int t = 0; t < 4; t++) {
                const float* kp = Ks + (8 * t + gy) * 128;
                uint32_t b[2] = { __float_as_uint(kp[i0]), __float_as_uint(kp[i1]) };
                mma8(s4[t], q[ks], b);
            }
        }

        // warp-local online softmax (rows qw+gy and qw+gy+8)
        float mx0 = -3.0e38f, mx1 = -3.0e38f;
#pragma unroll
        for (int t = 0; t < 4; t++) {
            mx0 = fmaxf(mx0, fmaxf(s4[t][0], s4[t][1]));
            mx1 = fmaxf(mx1, fmaxf(s4[t][2], s4[t][3]));
        }
        mx0 = fmaxf(mx0, __shfl_xor_sync(0xffffffffu, mx0, 1));
        mx0 = fmaxf(mx0, __shfl_xor_sync(0xffffffffu, mx0, 2));
        mx1 = fmaxf(mx1, __shfl_xor_sync(0xffffffffu, mx1, 1));
        mx1 = fmaxf(mx1, __shfl_xor_sync(0xffffffffu, mx1, 2));

        float mn0 = fmaxf(m0, mx0), mn1 = fmaxf(m1, mx1);
        float al0 = __expf(m0 - mn0), al1 = __expf(m1 - mn1);
        float sum0 = 0.0f, sum1 = 0.0f;
#pragma unroll
        for (int t = 0; t < 4; t++) {
            s4[t][0] = __expf(s4[t][0] - mn0);
            s4[t][1] = __expf(s4[t][1] - mn0);
            s4[t][2] = __expf(s4[t][2] - mn1);
            s4[t][3] = __expf(s4[t][3] - mn1);
            sum0 += s4[t][0] + s4[t][1];
            sum1 += s4[t][2] + s4[t][3];
        }
        sum0 += __shfl_xor_sync(0xffffffffu, sum0, 1);
        sum0 += __shfl_xor_sync(0xffffffffu, sum0, 2);
        sum1 += __shfl_xor_sync(0xffffffffu, sum1, 1);
        sum1 += __shfl_xor_sync(0xffffffffu, sum1, 2);

        l0 = l0 * al0 + sum0;  m0 = mn0;
        l1 = l1 * al1 + sum1;  m1 = mn1;

#pragma unroll
        for (int dt = 0; dt < 16; dt++) {
            o[dt][0] *= al0; o[dt][1] *= al0;
            o[dt][2] *= al1; o[dt][3] *= al1;
        }

        // P -> smem (tf32-rounded), per-warp region
#pragma unroll
        for (int t = 0; t < 4; t++) {
            *(float2*)&Ps[(qw + gy)     * LPV + 8 * t + 2 * gx] =
                make_float2(f2tff(s4[t][0]), f2tff(s4[t][1]));
            *(float2*)&Ps[(qw + gy + 8) * LPV + 8 * t + 2 * gx] =
                make_float2(f2tff(s4[t][2]), f2tff(s4[t][3]));
        }
        __syncwarp();

        // O += P . V : warp tile 16 x 128, k = 32
#pragma unroll
        for (int ks = 0; ks < 4; ks++) {
            const int k0 = ks * 8;
            const int i0 = ((2 * ks)     ^ gy) * 4 + gx;
            const int i1 = ((2 * ks + 1) ^ gy) * 4 + gx;
            uint32_t a[4];
            const float* pp = Ps + (qw + gy) * LPV + k0;
            a[0] = __float_as_uint(pp[gx]);
            a[1] = __float_as_uint(pp[8 * LPV + gx]);
            a[2] = __float_as_uint(pp[gx + 4]);
            a[3] = __float_as_uint(pp[8 * LPV + gx + 4]);
#pragma unroll
            for (int dt = 0; dt < 16; dt++) {
                const float* vp = Vs + (8 * dt + gy) * 32;
                uint32_t b[2] = { __float_as_uint(vp[i0]), __float_as_uint(vp[i1]) };
                mma8(o[dt], a, b);
            }
        }
    }

    // finalize: /l, tf32-round (input of out-proj), write [B,T,NH*HD]
    const int b = bh >> 4, h = bh & 15;
    const float inv0 = 1.0f / l0, inv1 = 1.0f / l1;
    const long t0 = q0 + qw + gy;
#pragma unroll
    for (int dt = 0; dt < 16; dt++) {
        int d = 8 * dt + 2 * gx;
        long base0 = ((long)b * TT + t0)     * HID + h * HD + d;
        long base1 = ((long)b * TT + t0 + 8) * HID + h * HD + d;
        *(float2*)&g_attn[base0] = make_float2(f2tff(o[dt][0] * inv0), f2tff(o[dt][1] * inv0));
        *(float2*)&g_attn[base1] = make_float2(f2tff(o[dt][2] * inv1), f2tff(o[dt][3] * inv1));
    }
}

// ---------------------------------------------------------------------------
extern "C" void kernel_launch(void* const* d_in, const int* in_sizes, int n_in,
                              void* d_out, int out_size)
{
    const float* x      = (const float*)d_in[0];
    const float* w_qkv  = (const float*)d_in[1];
    const float* w_proj = (const float*)d_in[2];
    const float* b_proj = (const float*)d_in[3];
    const float* cosT   = (const float*)d_in[4];
    const float* sinT   = (const float*)d_in[5];
    float* out = (float*)d_out;

    cudaFuncSetAttribute(gemm_kernel<0>,
                         cudaFuncAttributeMaxDynamicSharedMemorySize, GEMM_SMEM);
    cudaFuncSetAttribute(gemm_kernel<1>,
                         cudaFuncAttributeMaxDynamicSharedMemorySize, GEMM_SMEM);
    cudaFuncSetAttribute(attn_kernel,
                         cudaFuncAttributeMaxDynamicSharedMemorySize, ATTN_SMEM);

    // 0) pre-round inputs to tf32
    round_kernel<0><<<1024, 256>>>(x,      MTOT * KDIM);
    round_kernel<1><<<1024, 256>>>(w_qkv,  3 * HID * KDIM);
    round_kernel<2><<<1024, 256>>>(w_proj, HID * KDIM);

    // 1) QKV proj + RoPE + scatter (V transposed)
    gemm_kernel<0><<<dim3(MTOT / 128, (3 * HID) / 256), 256, GEMM_SMEM>>>(
        cosT, sinT, nullptr, nullptr);

    // 2) attention
    attn_kernel<<<dim3(TT / QT, BB * NH), 256, ATTN_SMEM>>>();

    // 3) out proj + bias
    gemm_kernel<1><<<dim3(MTOT / 128, HID / 256), 256, GEMM_SMEM>>>(
        nullptr, nullptr, b_proj, out);
}

// round 6
// speedup vs baseline: 1.1502x; 1.1502x over previous
#include <cuda_runtime.h>
#include <cstdint>

// Problem constants
#define BB   4
#define TT   2048
#define HID  2048
#define NH   16
#define HD   128
#define MTOT (BB * TT)          // 8192
#define KDIM 2048

// Scratch (device globals; allocation-free rule)
__device__ float g_x    [(size_t)MTOT * KDIM];        // tf32-rounded x
__device__ float g_wqkv [(size_t)3 * HID * KDIM];     // tf32-rounded w_qkv
__device__ float g_wproj[(size_t)HID * KDIM];         // tf32-rounded w_proj
__device__ float g_Q [(size_t)BB * NH * TT * HD];
__device__ float g_K [(size_t)BB * NH * TT * HD];
__device__ float g_Vt[(size_t)BB * NH * HD * TT];     // V^T: [bh][d][t]
__device__ float g_attn[(size_t)MTOT * HID];          // tf32-rounded attn out

// ---------------------------------------------------------------------------
// helpers
// ---------------------------------------------------------------------------
__device__ __forceinline__ float f2tff(float x) {
    uint32_t r;
    asm("cvt.rna.tf32.f32 %0, %1;" : "=r"(r) : "f"(x));
    return __uint_as_float(r);
}
__device__ __forceinline__ void mma8(float* c, const uint32_t* a, const uint32_t* b) {
    asm volatile(
        "mma.sync.aligned.m16n8k8.row.col.f32.tf32.tf32.f32 "
        "{%0,%1,%2,%3},{%4,%5,%6,%7},{%8,%9},{%0,%1,%2,%3};\n"
        : "+f"(c[0]), "+f"(c[1]), "+f"(c[2]), "+f"(c[3])
        : "r"(a[0]), "r"(a[1]), "r"(a[2]), "r"(a[3]), "r"(b[0]), "r"(b[1]));
}
__device__ __forceinline__ uint32_t smem_u32(const void* p) {
    return (uint32_t)__cvta_generic_to_shared(p);
}
#define LDSM4(r0, r1, r2, r3, addr) \
    asm volatile("ldmatrix.sync.aligned.m8n8.x4.shared.b16 {%0,%1,%2,%3}, [%4];\n" \
                 : "=r"(r0), "=r"(r1), "=r"(r2), "=r"(r3) : "r"(addr))
#define CP16(dst_u32, src_ptr) \
    asm volatile("cp.async.cg.shared.global [%0], [%1], 16;\n" :: "r"(dst_u32), "l"(src_ptr))
#define CP_COMMIT() asm volatile("cp.async.commit_group;\n" ::)
#define CP_WAIT1()  asm volatile("cp.async.wait_group 1;\n" ::)

// ---------------------------------------------------------------------------
// pre-round inputs to tf32
// ---------------------------------------------------------------------------
template <int WHICH>
__global__ void round_kernel(const float* __restrict__ src, int n)
{
    float* dst = (WHICH == 0) ? g_x : (WHICH == 1) ? g_wqkv : g_wproj;
    int stride = gridDim.x * blockDim.x * 4;
    for (int i = (blockIdx.x * blockDim.x + threadIdx.x) * 4; i < n; i += stride) {
        float4 v = *(const float4*)(src + i);
        *(float4*)(dst + i) = make_float4(f2tff(v.x), f2tff(v.y), f2tff(v.z), f2tff(v.w));
    }
}

// ---------------------------------------------------------------------------
// GEMM: C[M,N] = A[M,K] * Bw[N,K]^T  via m16n8k8 tf32 mma + ldmatrix frags.
// Block 128x128x32, 256 thr = 8 warps (2m x 4n), warp tile 64x32.
// 3-stage cp.async, ONE __syncthreads per k-iter. 2 CTAs/SM.
// smem rows: 32 floats, 8 f4 chunks, chunk col' = c4 ^ (row & 7).
// ---------------------------------------------------------------------------
#define GSTAGES 3
#define GEMM_SMEM (GSTAGES * 2 * 128 * 32 * 4)   // 98304 bytes

template <int MODE>
__global__ __launch_bounds__(256, 2)
void gemm_kernel(const float* __restrict__ cosT,
                 const float* __restrict__ sinT,
                 const float* __restrict__ bias,
                 float* __restrict__ Cout)
{
    extern __shared__ float sm[];
    float* As = sm;                        // GSTAGES * 4096
    float* Bs = sm + GSTAGES * 4096;

    const int tid  = threadIdx.x;
    const int lane = tid & 31;
    const int w    = tid >> 5;
    const int gy   = lane >> 2;   // 0..7
    const int gx   = lane & 3;    // 0..3
    const int wm   = (w >> 2) * 64;
    const int wn   = (w & 3) * 32;
    const long row0 = (long)blockIdx.x * 128;
    const long col0 = (long)blockIdx.y * 128;

    const float* __restrict__ Ap = (MODE == 0) ? g_x    : g_attn;
    const float* __restrict__ Bp = (MODE == 0) ? g_wqkv : g_wproj;

    // cp.async load maps (4 float4 per operand per stage per thread)
    int lr[4], lc4[4], soff[4];
#pragma unroll
    for (int j = 0; j < 4; j++) {
        int f = tid + j * 256;
        lr[j]  = f >> 3;  lc4[j] = f & 7;
        soff[j] = (lr[j] * 32 + ((lc4[j] ^ (lr[j] & 7)) * 4)) * 4;
    }
    const uint32_t sA = smem_u32(As);
    const uint32_t sB = smem_u32(Bs);

    // ldmatrix lane constants
    const int l7 = lane & 7;
    const int ha = (lane >> 4) & 1;                 // A: k-half
    const int ra = wm + l7 + 8 * ((lane >> 3) & 1); // A: row base (add 16s)
    const int hb = (lane >> 3) & 1;                 // B: k-half
    const int rb = wn + l7 + 8 * ((lane >> 4) & 1); // B: row base (add 16*tp)

    auto issue = [&](int kb, int slot) {
        if (kb < KDIM) {
            const uint32_t ba = sA + slot * 16384;
            const uint32_t bb = sB + slot * 16384;
#pragma unroll
            for (int j = 0; j < 4; j++) {
                CP16(ba + soff[j], Ap + (row0 + lr[j]) * KDIM + kb + lc4[j] * 4);
                CP16(bb + soff[j], Bp + (col0 + lr[j]) * KDIM + kb + lc4[j] * 4);
            }
        }
        CP_COMMIT();
    };

    float acc[4][4][4];
#pragma unroll
    for (int s = 0; s < 4; s++)
#pragma unroll
        for (int t = 0; t < 4; t++)
#pragma unroll
            for (int j = 0; j < 4; j++) acc[s][t][j] = 0.0f;

    issue(0, 0);
    issue(32, 1);

    for (int it = 0; it < KDIM / 32; it++) {
        CP_WAIT1();
        __syncthreads();
        issue((it + 2) * 32, (it + 2) % GSTAGES);

        const uint32_t Sa = sA + (it % GSTAGES) * 16384;
        const uint32_t Sb = sB + (it % GSTAGES) * 16384;
#pragma unroll
        for (int ks = 0; ks < 4; ks++) {
            const int ca = ((2 * ks + ha) ^ l7) * 16;   // A chunk byte offset
            const int cb = ((2 * ks + hb) ^ l7) * 16;   // B chunk byte offset
            uint32_t af[4][4], bf[4][2];
#pragma unroll
            for (int s = 0; s < 4; s++)
                LDSM4(af[s][0], af[s][1], af[s][2], af[s][3],
                      Sa + (ra + 16 * s) * 128 + ca);
            LDSM4(bf[0][0], bf[0][1], bf[1][0], bf[1][1], Sb + rb * 128 + cb);
            LDSM4(bf[2][0], bf[2][1], bf[3][0], bf[3][1], Sb + (rb + 16) * 128 + cb);
#pragma unroll
            for (int s = 0; s < 4; s++)
#pragma unroll
                for (int t = 0; t < 4; t++)
                    mma8(acc[s][t], af[s], bf[t]);
        }
    }

    // Epilogue. rows: row0+wm+16s+gy+8h; cols: col0+wn+8t+2gx(+1).
    if (MODE == 0) {
        const int sec  = (int)(col0 >> 11);          // 0=Q 1=K 2=V
        const int head = ((int)col0 >> 7) & 15;
        const float qscale = 0.08838834764831845f;   // 1/sqrt(128)
#pragma unroll
        for (int s = 0; s < 4; s++)
#pragma unroll
            for (int t = 0; t < 4; t++) {
                const int d = wn + 8 * t + 2 * gx;
                const int p = d >> 1;
#pragma unroll
                for (int h = 0; h < 2; h++) {
                    long r = row0 + wm + 16 * s + gy + 8 * h;
                    int  b  = (int)(r >> 11);
                    int  tt = (int)r & 2047;
                    float v0 = acc[s][t][2 * h + 0];
                    float v1 = acc[s][t][2 * h + 1];
                    if (sec < 2) {
                        float c  = cosT[tt * 64 + p];
                        float sn = sinT[tt * 64 + p];
                        float e = v0, o = v1;
                        v0 = e * c - o * sn;
                        v1 = e * sn + o * c;
                        if (sec == 0) { v0 *= qscale; v1 *= qscale; }
                    }
                    v0 = f2tff(v0); v1 = f2tff(v1);
                    long bh = (long)b * NH + head;
                    if (sec == 2) {
                        g_Vt[(bh * HD + d)     * TT + tt] = v0;
                        g_Vt[(bh * HD + d + 1) * TT + tt] = v1;
                    } else {
                        float* dst = (sec == 0) ? g_Q : g_K;
                        *(float2*)&dst[(bh * TT + tt) * HD + d] = make_float2(v0, v1);
                    }
                }
            }
    } else {
#pragma unroll
        for (int t = 0; t < 4; t++) {
            const long n = col0 + wn + 8 * t + 2 * gx;
            float2 bv = *(const float2*)&bias[n];
#pragma unroll
            for (int s = 0; s < 4; s++)
#pragma unroll
                for (int h = 0; h < 2; h++) {
                    long r = row0 + wm + 16 * s + gy + 8 * h;
                    *(float2*)&Cout[r * HID + n] =
                        make_float2(acc[s][t][2 * h] + bv.x, acc[s][t][2 * h + 1] + bv.y);
                }
        }
    }
}

// ---------------------------------------------------------------------------
// Flash attention via tf32 mma + ldmatrix.
// One block per (bh, 128-row q tile). KV tiles of 32. 8 warps, each 16 q rows.
// Q fragments in registers (loaded once). K/V: 3-stage cp.async, 1 sync/iter.
// smem floats: K 3*4096, V 3*4096, P 128*36.
// ---------------------------------------------------------------------------
#define QT  128
#define KVT 32
#define LPV 36
#define ATTN_SMEM ((3 * 4096 * 2 + QT * LPV) * 4)

__global__ __launch_bounds__(256, 1)
void attn_kernel()
{
    extern __shared__ float sm[];
    float* Kst = sm;                  // 3 * 32*128
    float* Vst = Kst + 3 * 4096;      // 3 * 128*32
    float* Ps  = Vst + 3 * 4096;      // 128*36

    const int tid  = threadIdx.x;
    const int lane = tid & 31;
    const int w    = tid >> 5;
    const int gy   = lane >> 2;
    const int gx   = lane & 3;
    const int bh   = blockIdx.y;
    const int q0   = blockIdx.x * QT;
    const int qw   = w * 16;

    const float* __restrict__ Qg = g_Q  + (long)bh * TT * HD;
    const float* __restrict__ Kg = g_K  + (long)bh * TT * HD;
    const float* __restrict__ Vg = g_Vt + (long)bh * HD * TT;

    const uint32_t sK = smem_u32(Kst);
    const uint32_t sV = smem_u32(Vst);
    const uint32_t sP = smem_u32(Ps);

    // ldmatrix lane constants
    const int l7 = lane & 7;
    const int hb = (lane >> 3) & 1;                   // k-half (B-type frags)
    const int rsel = (lane >> 4) & 1;                 // tile-pair row select
    const int rkv  = 8 * rsel + l7;                   // K/V row base (+16*tp)
    const int rowp = qw + l7 + 8 * ((lane >> 3) & 1); // P row
    const int hp   = (lane >> 4) & 1;                 // P k-half

    // ---- Stage Q through smem (Kst area), pull fragments into registers ----
    uint32_t q[16][4];
    {
        float* Qtmp = Kst;
#pragma unroll
        for (int i = 0; i < 16; i++) {
            int f = tid + i * 256;
            int r = f >> 5, c4 = f & 31;
            int cs = (c4 & 24) | ((c4 & 7) ^ (r & 7));
            *(float4*)&Qtmp[r * 128 + cs * 4] =
                *(const float4*)&Qg[(long)(q0 + r) * HD + c4 * 4];
        }
        __syncthreads();
        // A-frag ldsm: rows qw + l7 + 8*((lane>>3)&1), chunk (2ks+hp)^l7
        const int rq = qw + l7 + 8 * ((lane >> 3) & 1);
        const uint32_t qbase = smem_u32(Qtmp) + rq * 512;
#pragma unroll
        for (int ks = 0; ks < 16; ks++) {
            const int c4 = 2 * ks + hp;
            const int cs = (c4 & 24) | ((c4 & 7) ^ l7);
            LDSM4(q[ks][0], q[ks][1], q[ks][2], q[ks][3], qbase + cs * 16);
        }
        __syncthreads();
    }

    auto issueKV = [&](int kv0, int slot) {
        if (kv0 < TT) {
#pragma unroll
            for (int i = 0; i < 4; i++) {
                int f = tid + i * 256;
                int r = f >> 5, c4 = f & 31;
                int cs = (c4 & 24) | ((c4 & 7) ^ (r & 7));
                CP16(sK + (slot * 4096 + r * 128 + cs * 4) * 4,
                     Kg + (long)(kv0 + r) * HD + c4 * 4);
            }
#pragma unroll
            for (int i = 0; i < 4; i++) {
                int f = tid + i * 256;
                int d = f >> 3, k4 = f & 7;
                CP16(sV + (slot * 4096 + d * 32 + ((k4 ^ (d & 7)) * 4)) * 4,
                     Vg + (long)d * TT + kv0 + k4 * 4);
            }
        }
        CP_COMMIT();
    };

    float o[16][4];
#pragma unroll
    for (int dt = 0; dt < 16; dt++)
#pragma unroll
        for (int j = 0; j < 4; j++) o[dt][j] = 0.0f;
    float m0 = -3.0e38f, m1 = -3.0e38f, l0 = 0.0f, l1 = 0.0f;

    issueKV(0, 0);
    issueKV(KVT, 1);

    for (int i = 0; i < TT / KVT; i++) {
        CP_WAIT1();
        __syncthreads();
        issueKV((i + 2) * KVT, (i + 2) % 3);

        const uint32_t Kb = sK + (i % 3) * 16384;
        const uint32_t Vb = sV + (i % 3) * 16384;

        // S = Q . K^T : warp tile 16 x 32, k = 128 (A = registers, B = ldsm)
        float s4[4][4];
#pragma unroll
        for (int t = 0; t < 4; t++)
#pragma unroll
            for (int j = 0; j < 4; j++) s4[t][j] = 0.0f;

#pragma unroll
        for (int ks = 0; ks < 16; ks++) {
            const int c4 = 2 * ks + hb;
            const int cs = ((c4 & 24) | ((c4 & 7) ^ l7)) * 16;
            uint32_t bf[4][2];
            LDSM4(bf[0][0], bf[0][1], bf[1][0], bf[1][1], Kb + rkv * 512 + cs);
            LDSM4(bf[2][0], bf[2][1], bf[3][0], bf[3][1], Kb + (rkv + 16) * 512 + cs);
#pragma unroll
            for (int t = 0; t < 4; t++)
                mma8(s4[t], q[ks], bf[t]);
        }

        // warp-local online softmax (rows qw+gy and qw+gy+8)
        float mx0 = -3.0e38f, mx1 = -3.0e38f;
#pragma unroll
        for (int t = 0; t < 4; t++) {
            mx0 = fmaxf(mx0, fmaxf(s4[t][0], s4[t][1]));
            mx1 = fmaxf(mx1, fmaxf(s4[t][2], s4[t][3]));
        }
        mx0 = fmaxf(mx0, __shfl_xor_sync(0xffffffffu, mx0, 1));
        mx0 = fmaxf(mx0, __shfl_xor_sync(0xffffffffu, mx0, 2));
        mx1 = fmaxf(mx1, __shfl_xor_sync(0xffffffffu, mx1, 1));
        mx1 = fmaxf(mx1, __shfl_xor_sync(0xffffffffu, mx1, 2));

        float mn0 = fmaxf(m0, mx0), mn1 = fmaxf(m1, mx1);
        float al0 = __expf(m0 - mn0), al1 = __expf(m1 - mn1);
        float sum0 = 0.0f, sum1 = 0.0f;
#pragma unroll
        for (int t = 0; t < 4; t++) {
            s4[t][0] = __expf(s4[t][0] - mn0);
            s4[t][1] = __expf(s4[t][1] - mn0);
            s4[t][2] = __expf(s4[t][2] - mn1);
            s4[t][3] = __expf(s4[t][3] - mn1);
            sum0 += s4[t][0] + s4[t][1];
            sum1 += s4[t][2] + s4[t][3];
        }
        sum0 += __shfl_xor_sync(0xffffffffu, sum0, 1);
        sum0 += __shfl_xor_sync(0xffffffffu, sum0, 2);
        sum1 += __shfl_xor_sync(0xffffffffu, sum1, 1);
        sum1 += __shfl_xor_sync(0xffffffffu, sum1, 2);

        l0 = l0 * al0 + sum0;  m0 = mn0;
        l1 = l1 * al1 + sum1;  m1 = mn1;

#pragma unroll
        for (int dt = 0; dt < 16; dt++) {
            o[dt][0] *= al0; o[dt][1] *= al0;
            o[dt][2] *= al1; o[dt][3] *= al1;
        }

        // P -> smem (tf32-rounded), per-warp region
#pragma unroll
        for (int t = 0; t < 4; t++) {
            *(float2*)&Ps[(qw + gy)     * LPV + 8 * t + 2 * gx] =
                make_float2(f2tff(s4[t][0]), f2tff(s4[t][1]));
            *(float2*)&Ps[(qw + gy + 8) * LPV + 8 * t + 2 * gx] =
                make_float2(f2tff(s4[t][2]), f2tff(s4[t][3]));
        }
        __syncwarp();

        // O += P . V : warp tile 16 x 128, k = 32 (A = P ldsm, B = V ldsm)
#pragma unroll
        for (int ks = 0; ks < 4; ks++) {
            uint32_t a[4];
            LDSM4(a[0], a[1], a[2], a[3],
                  sP + (rowp * LPV + 8 * ks + 4 * hp) * 4);
            const int cs = ((2 * ks + hb) ^ l7) * 16;
#pragma unroll
            for (int tp = 0; tp < 8; tp++) {
                uint32_t bf[2][2];
                LDSM4(bf[0][0], bf[0][1], bf[1][0], bf[1][1],
                      Vb + (rkv + 16 * tp) * 128 + cs);
                mma8(o[2 * tp],     a, bf[0]);
                mma8(o[2 * tp + 1], a, bf[1]);
            }
        }
    }

    // finalize: /l, tf32-round (input of out-proj), write [B,T,NH*HD]
    const int b = bh >> 4, h = bh & 15;
    const float inv0 = 1.0f / l0, inv1 = 1.0f / l1;
    const long t0 = q0 + qw + gy;
#pragma unroll
    for (int dt = 0; dt < 16; dt++) {
        int d = 8 * dt + 2 * gx;
        long base0 = ((long)b * TT + t0)     * HID + h * HD + d;
        long base1 = ((long)b * TT + t0 + 8) * HID + h * HD + d;
        *(float2*)&g_attn[base0] = make_float2(f2tff(o[dt][0] * inv0), f2tff(o[dt][1] * inv0));
        *(float2*)&g_attn[base1] = make_float2(f2tff(o[dt][2] * inv1), f2tff(o[dt][3] * inv1));
    }
}

// ---------------------------------------------------------------------------
extern "C" void kernel_launch(void* const* d_in, const int* in_sizes, int n_in,
                              void* d_out, int out_size)
{
    const float* x      = (const float*)d_in[0];
    const float* w_qkv  = (const float*)d_in[1];
    const float* w_proj = (const float*)d_in[2];
    const float* b_proj = (const float*)d_in[3];
    const float* cosT   = (const float*)d_in[4];
    const float* sinT   = (const float*)d_in[5];
    float* out = (float*)d_out;

    cudaFuncSetAttribute(gemm_kernel<0>,
                         cudaFuncAttributeMaxDynamicSharedMemorySize, GEMM_SMEM);
    cudaFuncSetAttribute(gemm_kernel<1>,
                         cudaFuncAttributeMaxDynamicSharedMemorySize, GEMM_SMEM);
    cudaFuncSetAttribute(attn_kernel,
                         cudaFuncAttributeMaxDynamicSharedMemorySize, ATTN_SMEM);

    // 0) pre-round inputs to tf32
    round_kernel<0><<<1024, 256>>>(x,      MTOT * KDIM);
    round_kernel<1><<<1024, 256>>>(w_qkv,  3 * HID * KDIM);
    round_kernel<2><<<1024, 256>>>(w_proj, HID * KDIM);

    // 1) QKV proj + RoPE + scatter (V transposed)
    gemm_kernel<0><<<dim3(MTOT / 128, (3 * HID) / 128), 256, GEMM_SMEM>>>(
        cosT, sinT, nullptr, nullptr);

    // 2) attention
    attn_kernel<<<dim3(TT / QT, BB * NH), 256, ATTN_SMEM>>>();

    // 3) out proj + bias
    gemm_kernel<1><<<dim3(MTOT / 128, HID / 128), 256, GEMM_SMEM>>>(
        nullptr, nullptr, b_proj, out);
}

// round 8
// speedup vs baseline: 2.1613x; 1.8790x over previous
#include <cuda_runtime.h>
#include <cuda_fp16.h>
#include <cstdint>

// Problem constants
#define BB   4
#define TT   2048
#define HID  2048
#define NH   16
#define HD   128
#define MTOT (BB * TT)          // 8192
#define KDIM 2048

// Scratch (device globals; allocation-free rule) — all fp16 operands
__device__ __half g_xh   [(size_t)MTOT * KDIM];
__device__ __half g_wqkvh[(size_t)3 * HID * KDIM];
__device__ __half g_wprojh[(size_t)HID * KDIM];
__device__ __half g_Qh [(size_t)BB * NH * TT * HD];
__device__ __half g_Kh [(size_t)BB * NH * TT * HD];
__device__ __half g_Vth[(size_t)BB * NH * HD * TT];   // V^T: [bh][d][t]
__device__ __half g_attnh[(size_t)MTOT * HID];

// ---------------------------------------------------------------------------
// helpers
// ---------------------------------------------------------------------------
__device__ __forceinline__ void mma16(float* c, const uint32_t* a, const uint32_t* b) {
    asm volatile(
        "mma.sync.aligned.m16n8k16.row.col.f32.f16.f16.f32 "
        "{%0,%1,%2,%3},{%4,%5,%6,%7},{%8,%9},{%0,%1,%2,%3};\n"
        : "+f"(c[0]), "+f"(c[1]), "+f"(c[2]), "+f"(c[3])
        : "r"(a[0]), "r"(a[1]), "r"(a[2]), "r"(a[3]), "r"(b[0]), "r"(b[1]));
}
__device__ __forceinline__ uint32_t smem_u32(const void* p) {
    return (uint32_t)__cvta_generic_to_shared(p);
}
#define LDSM4(r0, r1, r2, r3, addr) \
    asm volatile("ldmatrix.sync.aligned.m8n8.x4.shared.b16 {%0,%1,%2,%3}, [%4];\n" \
                 : "=r"(r0), "=r"(r1), "=r"(r2), "=r"(r3) : "r"(addr))
#define CP16(dst_u32, src_ptr) \
    asm volatile("cp.async.cg.shared.global [%0], [%1], 16;\n" :: "r"(dst_u32), "l"(src_ptr))
#define CP_COMMIT() asm volatile("cp.async.commit_group;\n" ::)
#define CP_WAIT1()  asm volatile("cp.async.wait_group 1;\n" ::)

// ---------------------------------------------------------------------------
// convert inputs fp32 -> fp16
// ---------------------------------------------------------------------------
template <int WHICH>
__global__ void round_kernel(const float* __restrict__ src, int n)
{
    __half* dst = (WHICH == 0) ? g_xh : (WHICH == 1) ? g_wqkvh : g_wprojh;
    int stride = gridDim.x * blockDim.x * 8;
    for (int i = (blockIdx.x * blockDim.x + threadIdx.x) * 8; i < n; i += stride) {
        float4 v0 = *(const float4*)(src + i);
        float4 v1 = *(const float4*)(src + i + 4);
        __half2 h0 = __floats2half2_rn(v0.x, v0.y);
        __half2 h1 = __floats2half2_rn(v0.z, v0.w);
        __half2 h2 = __floats2half2_rn(v1.x, v1.y);
        __half2 h3 = __floats2half2_rn(v1.z, v1.w);
        uint4 u;
        u.x = *(uint32_t*)&h0;  u.y = *(uint32_t*)&h1;
        u.z = *(uint32_t*)&h2;  u.w = *(uint32_t*)&h3;
        *(uint4*)(dst + i) = u;
    }
}

// ---------------------------------------------------------------------------
// fp16 GEMM: C[M,N] = A[M,K] * Bw[N,K]^T via m16n8k16 mma (fp32 accum).
// Block 128x128, K-block 64 halfs. 256 thr = 8 warps (2m x 4n), warp 64x32.
// 3-stage cp.async, 1 sync/iter, 2 CTAs/SM.
// smem rows: 64 halfs = 128B = 8 chunks of 16B, chunk col' = c8 ^ (row&7).
// MODE 0: A=g_xh, Bw=g_wqkvh; RoPE+qscale epilogue -> g_Qh/g_Kh/g_Vth (fp16).
// MODE 1: A=g_attnh, Bw=g_wprojh; +bias -> Cout (fp32).
// ---------------------------------------------------------------------------
#define BK 64
#define GSTAGES 3
#define STG_B 16384                       // bytes per A (or B) stage
#define GEMM_SMEM (GSTAGES * 2 * STG_B)   // 98304
#define NKIT (KDIM / BK)                  // 32

template <int MODE>
__global__ __launch_bounds__(256, 2)
void gemm_kernel(const float* __restrict__ cosT,
                 const float* __restrict__ sinT,
                 const float* __restrict__ bias,
                 float* __restrict__ Cout)
{
    extern __shared__ __half smh[];
    const uint32_t sA = smem_u32(smh);
    const uint32_t sB = sA + GSTAGES * STG_B;

    const int tid  = threadIdx.x;
    const int lane = tid & 31;
    const int w    = tid >> 5;
    const int gy   = lane >> 2;
    const int gx   = lane & 3;
    const int wm   = (w >> 2) * 64;
    const int wn   = (w & 3) * 32;
    const long row0 = (long)blockIdx.x * 128;
    const long col0 = (long)blockIdx.y * 128;

    const __half* __restrict__ Ap = (MODE == 0) ? g_xh    : g_attnh;
    const __half* __restrict__ Bp = (MODE == 0) ? g_wqkvh : g_wprojh;

    // cp.async maps: 4 chunks (16B = 8 halfs) per operand per thread
    int lr[4], lc8[4], soff[4];
#pragma unroll
    for (int j = 0; j < 4; j++) {
        int f = tid + j * 256;
        lr[j]  = f >> 3;           // 0..127
        lc8[j] = f & 7;            // chunk 0..7
        soff[j] = lr[j] * 128 + ((lc8[j] ^ (lr[j] & 7)) * 16);
    }

    // ldmatrix lane constants
    const int l7 = lane & 7;
    const int ha = (lane >> 4) & 1;                 // A k-chunk select
    const int ra = wm + l7 + 8 * ((lane >> 3) & 1); // A row base (+16s)
    const int hb = (lane >> 3) & 1;                 // B k-chunk select
    const int rb = wn + l7 + 8 * ((lane >> 4) & 1); // B row base (+16*tp)

    auto issue = [&](int kb, int slot) {
        if (kb < KDIM) {
            const uint32_t ba = sA + slot * STG_B;
            const uint32_t bb = sB + slot * STG_B;
#pragma unroll
            for (int j = 0; j < 4; j++) {
                CP16(ba + soff[j], Ap + (row0 + lr[j]) * KDIM + kb + lc8[j] * 8);
                CP16(bb + soff[j], Bp + (col0 + lr[j]) * KDIM + kb + lc8[j] * 8);
            }
        }
        CP_COMMIT();
    };

    float acc[4][4][4];
#pragma unroll
    for (int s = 0; s < 4; s++)
#pragma unroll
        for (int t = 0; t < 4; t++)
#pragma unroll
            for (int j = 0; j < 4; j++) acc[s][t][j] = 0.0f;

    issue(0, 0);
    issue(BK, 1);

    for (int it = 0; it < NKIT; it++) {
        CP_WAIT1();
        __syncthreads();
        issue((it + 2) * BK, (it + 2) % GSTAGES);

        const uint32_t Sa = sA + (it % GSTAGES) * STG_B;
        const uint32_t Sb = sB + (it % GSTAGES) * STG_B;
#pragma unroll
        for (int ks = 0; ks < 4; ks++) {         // 4 k-steps of 16 halfs
            const int ca = ((2 * ks + ha) ^ l7) * 16;
            const int cb = ((2 * ks + hb) ^ l7) * 16;
            uint32_t af[4][4], bf[4][2];
#pragma unroll
            for (int s = 0; s < 4; s++)
                LDSM4(af[s][0], af[s][1], af[s][2], af[s][3],
                      Sa + (ra + 16 * s) * 128 + ca);
            LDSM4(bf[0][0], bf[0][1], bf[1][0], bf[1][1], Sb + rb * 128 + cb);
            LDSM4(bf[2][0], bf[2][1], bf[3][0], bf[3][1], Sb + (rb + 16) * 128 + cb);
#pragma unroll
            for (int s = 0; s < 4; s++)
#pragma unroll
                for (int t = 0; t < 4; t++)
                    mma16(acc[s][t], af[s], bf[t]);
        }
    }

    // Epilogue. rows: row0+wm+16s+gy+8h; cols: col0+wn+8t+2gx(+1).
    if (MODE == 0) {
        const int sec  = (int)(col0 >> 11);          // 0=Q 1=K 2=V
        const int head = ((int)col0 >> 7) & 15;
        const float qscale = 0.08838834764831845f;   // 1/sqrt(128)
#pragma unroll
        for (int s = 0; s < 4; s++)
#pragma unroll
            for (int t = 0; t < 4; t++) {
                const int d = wn + 8 * t + 2 * gx;
                const int p = d >> 1;
#pragma unroll
                for (int h = 0; h < 2; h++) {
                    long r = row0 + wm + 16 * s + gy + 8 * h;
                    int  b  = (int)(r >> 11);
                    int  tt = (int)r & 2047;
                    float v0 = acc[s][t][2 * h + 0];
                    float v1 = acc[s][t][2 * h + 1];
                    if (sec < 2) {
                        float c  = cosT[tt * 64 + p];
                        float sn = sinT[tt * 64 + p];
                        float e = v0, o = v1;
                        v0 = e * c - o * sn;
                        v1 = e * sn + o * c;
                        if (sec == 0) { v0 *= qscale; v1 *= qscale; }
                    }
                    long bh = (long)b * NH + head;
                    if (sec == 2) {
                        g_Vth[(bh * HD + d)     * TT + tt] = __float2half_rn(v0);
                        g_Vth[(bh * HD + d + 1) * TT + tt] = __float2half_rn(v1);
                    } else {
                        __half* dst = (sec == 0) ? g_Qh : g_Kh;
                        *(__half2*)&dst[(bh * TT + tt) * HD + d] =
                            __floats2half2_rn(v0, v1);
                    }
                }
            }
    } else {
#pragma unroll
        for (int t = 0; t < 4; t++) {
            const long n = col0 + wn + 8 * t + 2 * gx;
            float2 bv = *(const float2*)&bias[n];
#pragma unroll
            for (int s = 0; s < 4; s++)
#pragma unroll
                for (int h = 0; h < 2; h++) {
                    long r = row0 + wm + 16 * s + gy + 8 * h;
                    *(float2*)&Cout[r * HID + n] =
                        make_float2(acc[s][t][2 * h] + bv.x, acc[s][t][2 * h + 1] + bv.y);
                }
        }
    }
}

// ---------------------------------------------------------------------------
// fp16 flash attention. One block per (bh, 128-q tile). KV tiles of 64.
// 8 warps x 16 q rows. Q frags in regs. 3-stage cp.async K/V, 1 sync/iter.
// Q/K rows: 128 halfs = 256B = 16 chunks, swizzle (c8&8)|((c8&7)^(r&7)).
// V^T/P rows: 64 halfs = 128B = 8 chunks, swizzle c8^(r&7).
// smem: K 3*16KB, V 3*16KB, P 16KB = 112KB.
// ---------------------------------------------------------------------------
#define QT  128
#define KVT 64
#define KSTG_B 16384
#define ATTN_SMEM (3 * KSTG_B + 3 * KSTG_B + 16384)   // 114688
#define NIT (TT / KVT)                                // 32

__global__ __launch_bounds__(256, 1)
void attn_kernel()
{
    extern __shared__ __half smh[];
    __half* Kst = smh;                    // 3 * 64*128
    __half* Vst = Kst + 3 * 8192;         // 3 * 128*64
    __half* Ps  = Vst + 3 * 8192;         // 128*64

    const int tid  = threadIdx.x;
    const int lane = tid & 31;
    const int w    = tid >> 5;
    const int gy   = lane >> 2;
    const int gx   = lane & 3;
    const int bh   = blockIdx.y;
    const int q0   = blockIdx.x * QT;
    const int qw   = w * 16;

    const __half* __restrict__ Qg = g_Qh  + (long)bh * TT * HD;
    const __half* __restrict__ Kg = g_Kh  + (long)bh * TT * HD;
    const __half* __restrict__ Vg = g_Vth + (long)bh * HD * TT;

    const uint32_t sK = smem_u32(Kst);
    const uint32_t sV = smem_u32(Vst);
    const uint32_t sP = smem_u32(Ps);

    const int l7  = lane & 7;
    const int hb  = (lane >> 3) & 1;
    const int hp  = (lane >> 4) & 1;
    const int rkv = 8 * ((lane >> 4) & 1) + l7;        // K/V row base (+16*tp)
    const int rowp = qw + l7 + 8 * ((lane >> 3) & 1);  // P/Q A-frag row

    // ---- Stage Q in smem (Kst area), pull m16n8k16 A-frags to registers ----
    uint32_t q[8][4];
    {
        __half* Qtmp = Kst;   // needs 128*128 halfs = 32KB; Kst region = 48KB
#pragma unroll
        for (int i = 0; i < 8; i++) {
            int f = tid + i * 256;
            int r = f >> 4, c8 = f & 15;
            int cs = (c8 & 8) | ((c8 & 7) ^ (r & 7));
            *(uint4*)&Qtmp[r * 128 + cs * 8] =
                *(const uint4*)&Qg[(long)(q0 + r) * HD + c8 * 8];
        }
        __syncthreads();
        const uint32_t qbase = smem_u32(Qtmp) + rowp * 256;
#pragma unroll
        for (int ks = 0; ks < 8; ks++) {
            const int c8 = 2 * ks + hp;
            const int cs = (c8 & 8) | ((c8 & 7) ^ l7);
            LDSM4(q[ks][0], q[ks][1], q[ks][2], q[ks][3], qbase + cs * 16);
        }
        __syncthreads();
    }

    auto issueKV = [&](int kv0, int slot) {
        if (kv0 < TT) {
#pragma unroll
            for (int i = 0; i < 4; i++) {           // K: 64 rows x 16 chunks
                int f = tid + i * 256;
                int r = f >> 4, c8 = f & 15;
                int cs = (c8 & 8) | ((c8 & 7) ^ (r & 7));
                CP16(sK + slot * KSTG_B + r * 256 + cs * 16,
                     Kg + (long)(kv0 + r) * HD + c8 * 8);
            }
#pragma unroll
            for (int i = 0; i < 4; i++) {           // V^T: 128 rows x 8 chunks
                int f = tid + i * 256;
                int d = f >> 3, c8 = f & 7;
                CP16(sV + slot * KSTG_B + d * 128 + ((c8 ^ (d & 7)) * 16),
                     Vg + (long)d * TT + kv0 + c8 * 8);
            }
        }
        CP_COMMIT();
    };

    float o[16][4];
#pragma unroll
    for (int dt = 0; dt < 16; dt++)
#pragma unroll
        for (int j = 0; j < 4; j++) o[dt][j] = 0.0f;
    float m0 = -3.0e38f, m1 = -3.0e38f, l0 = 0.0f, l1 = 0.0f;

    issueKV(0, 0);
    issueKV(KVT, 1);

    for (int i = 0; i < NIT; i++) {
        CP_WAIT1();
        __syncthreads();
        issueKV((i + 2) * KVT, (i + 2) % 3);

        const uint32_t Kb = sK + (i % 3) * KSTG_B;
        const uint32_t Vb = sV + (i % 3) * KSTG_B;

        // S = Q.K^T : warp 16 x 64, k = 128 (8 k-steps)
        float s4[8][4];
#pragma unroll
        for (int t = 0; t < 8; t++)
#pragma unroll
            for (int j = 0; j < 4; j++) s4[t][j] = 0.0f;

#pragma unroll
        for (int ks = 0; ks < 8; ks++) {
            const int c8 = 2 * ks + hb;
            const int cs = ((c8 & 8) | ((c8 & 7) ^ l7)) * 16;
#pragma unroll
            for (int tp = 0; tp < 4; tp++) {
                uint32_t bf[2][2];
                LDSM4(bf[0][0], bf[0][1], bf[1][0], bf[1][1],
                      Kb + (rkv + 16 * tp) * 256 + cs);
                mma16(s4[2 * tp],     q[ks], bf[0]);
                mma16(s4[2 * tp + 1], q[ks], bf[1]);
            }
        }

        // warp-local online softmax (rows qw+gy, qw+gy+8)
        float mx0 = -3.0e38f, mx1 = -3.0e38f;
#pragma unroll
        for (int t = 0; t < 8; t++) {
            mx0 = fmaxf(mx0, fmaxf(s4[t][0], s4[t][1]));
            mx1 = fmaxf(mx1, fmaxf(s4[t][2], s4[t][3]));
        }
        mx0 = fmaxf(mx0, __shfl_xor_sync(0xffffffffu, mx0, 1));
        mx0 = fmaxf(mx0, __shfl_xor_sync(0xffffffffu, mx0, 2));
        mx1 = fmaxf(mx1, __shfl_xor_sync(0xffffffffu, mx1, 1));
        mx1 = fmaxf(mx1, __shfl_xor_sync(0xffffffffu, mx1, 2));

        float mn0 = fmaxf(m0, mx0), mn1 = fmaxf(m1, mx1);
        float al0 = __expf(m0 - mn0), al1 = __expf(m1 - mn1);
        float sum0 = 0.0f, sum1 = 0.0f;
#pragma unroll
        for (int t = 0; t < 8; t++) {
            s4[t][0] = __expf(s4[t][0] - mn0);
            s4[t][1] = __expf(s4[t][1] - mn0);
            s4[t][2] = __expf(s4[t][2] - mn1);
            s4[t][3] = __expf(s4[t][3] - mn1);
            sum0 += s4[t][0] + s4[t][1];
            sum1 += s4[t][2] + s4[t][3];
        }
        sum0 += __shfl_xor_sync(0xffffffffu, sum0, 1);
        sum0 += __shfl_xor_sync(0xffffffffu, sum0, 2);
        sum1 += __shfl_xor_sync(0xffffffffu, sum1, 1);
        sum1 += __shfl_xor_sync(0xffffffffu, sum1, 2);

        l0 = l0 * al0 + sum0;  m0 = mn0;
        l1 = l1 * al1 + sum1;  m1 = mn1;

#pragma unroll
        for (int dt = 0; dt < 16; dt++) {
            o[dt][0] *= al0; o[dt][1] *= al0;
            o[dt][2] *= al1; o[dt][3] *= al1;
        }

        // P -> smem fp16 (swizzled), per-warp region
#pragma unroll
        for (int t = 0; t < 8; t++) {
            int cs = t ^ gy;     // (row&7) == gy for both rows
            *(__half2*)&Ps[(qw + gy)     * 64 + cs * 8 + gx * 2] =
                __floats2half2_rn(s4[t][0], s4[t][1]);
            *(__half2*)&Ps[(qw + gy + 8) * 64 + cs * 8 + gx * 2] =
                __floats2half2_rn(s4[t][2], s4[t][3]);
        }
        __syncwarp();

        // O += P.V : warp 16 x 128, k = 64 (4 k-steps)
#pragma unroll
        for (int ks = 0; ks < 4; ks++) {
            uint32_t a[4];
            LDSM4(a[0], a[1], a[2], a[3],
                  sP + rowp * 128 + (((2 * ks + hp) ^ l7) * 16));
            const int cs = ((2 * ks + hb) ^ l7) * 16;
#pragma unroll
            for (int tp = 0; tp < 8; tp++) {
                uint32_t bf[2][2];
                LDSM4(bf[0][0], bf[0][1], bf[1][0], bf[1][1],
                      Vb + (rkv + 16 * tp) * 128 + cs);
                mma16(o[2 * tp],     a, bf[0]);
                mma16(o[2 * tp + 1], a, bf[1]);
            }
        }
    }

    // finalize: /l, fp16 (input of out-proj), write [B,T,NH*HD]
    const int b = bh >> 4, h = bh & 15;
    const float inv0 = 1.0f / l0, inv1 = 1.0f / l1;
    const long t0 = q0 + qw + gy;
#pragma unroll
    for (int dt = 0; dt < 16; dt++) {
        int d = 8 * dt + 2 * gx;
        long base0 = ((long)b * TT + t0)     * HID + h * HD + d;
        long base1 = ((long)b * TT + t0 + 8) * HID + h * HD + d;
        *(__half2*)&g_attnh[base0] = __floats2half2_rn(o[dt][0] * inv0, o[dt][1] * inv0);
        *(__half2*)&g_attnh[base1] = __floats2half2_rn(o[dt][2] * inv1, o[dt][3] * inv1);
    }
}

// ---------------------------------------------------------------------------
extern "C" void kernel_launch(void* const* d_in, const int* in_sizes, int n_in,
                              void* d_out, int out_size)
{
    const float* x      = (const float*)d_in[0];
    const float* w_qkv  = (const float*)d_in[1];
    const float* w_proj = (const float*)d_in[2];
    const float* b_proj = (const float*)d_in[3];
    const float* cosT   = (const float*)d_in[4];
    const float* sinT   = (const float*)d_in[5];
    float* out = (float*)d_out;

    cudaFuncSetAttribute(gemm_kernel<0>,
                         cudaFuncAttributeMaxDynamicSharedMemorySize, GEMM_SMEM);
    cudaFuncSetAttribute(gemm_kernel<1>,
                         cudaFuncAttributeMaxDynamicSharedMemorySize, GEMM_SMEM);
    cudaFuncSetAttribute(attn_kernel,
                         cudaFuncAttributeMaxDynamicSharedMemorySize, ATTN_SMEM);

    // 0) convert inputs to fp16
    round_kernel<0><<<1024, 256>>>(x,      MTOT * KDIM);
    round_kernel<1><<<1024, 256>>>(w_qkv,  3 * HID * KDIM);
    round_kernel<2><<<1024, 256>>>(w_proj, HID * KDIM);

    // 1) QKV proj (fp16 mma) + RoPE + scatter (V transposed)
    gemm_kernel<0><<<dim3(MTOT / 128, (3 * HID) / 128), 256, GEMM_SMEM>>>(
        cosT, sinT, nullptr, nullptr);

    // 2) attention (fp16 mma)
    attn_kernel<<<dim3(TT / QT, BB * NH), 256, ATTN_SMEM>>>();

    // 3) out proj (fp16 mma) + bias
    gemm_kernel<1><<<dim3(MTOT / 128, HID / 128), 256, GEMM_SMEM>>>(
        nullptr, nullptr, b_proj, out);
}

// round 9
// speedup vs baseline: 2.1752x; 1.0064x over previous
#include <cuda_runtime.h>
#include <cuda_fp16.h>
#include <cstdint>

// Problem constants
#define BB   4
#define TT   2048
#define HID  2048
#define NH   16
#define HD   128
#define MTOT (BB * TT)          // 8192
#define KDIM 2048

// Scratch (device globals; allocation-free rule) — all fp16 operands
__device__ __half g_xh   [(size_t)MTOT * KDIM];
__device__ __half g_wqkvh[(size_t)3 * HID * KDIM];
__device__ __half g_wprojh[(size_t)HID * KDIM];
__device__ __half g_Qh [(size_t)BB * NH * TT * HD];
__device__ __half g_Kh [(size_t)BB * NH * TT * HD];
__device__ __half g_Vth[(size_t)BB * NH * HD * TT];   // V^T: [bh][d][t]
__device__ __half g_attnh[(size_t)MTOT * HID];

// ---------------------------------------------------------------------------
// helpers
// ---------------------------------------------------------------------------
__device__ __forceinline__ void mma16(float* c, const uint32_t* a, const uint32_t* b) {
    asm volatile(
        "mma.sync.aligned.m16n8k16.row.col.f32.f16.f16.f32 "
        "{%0,%1,%2,%3},{%4,%5,%6,%7},{%8,%9},{%0,%1,%2,%3};\n"
        : "+f"(c[0]), "+f"(c[1]), "+f"(c[2]), "+f"(c[3])
        : "r"(a[0]), "r"(a[1]), "r"(a[2]), "r"(a[3]), "r"(b[0]), "r"(b[1]));
}
__device__ __forceinline__ uint32_t smem_u32(const void* p) {
    return (uint32_t)__cvta_generic_to_shared(p);
}
#define LDSM4(r0, r1, r2, r3, addr) \
    asm volatile("ldmatrix.sync.aligned.m8n8.x4.shared.b16 {%0,%1,%2,%3}, [%4];\n" \
                 : "=r"(r0), "=r"(r1), "=r"(r2), "=r"(r3) : "r"(addr))
#define CP16(dst_u32, src_ptr) \
    asm volatile("cp.async.cg.shared.global [%0], [%1], 16;\n" :: "r"(dst_u32), "l"(src_ptr))
#define CP_COMMIT() asm volatile("cp.async.commit_group;\n" ::)
#define CP_WAIT2()  asm volatile("cp.async.wait_group 2;\n" ::)

// ---------------------------------------------------------------------------
// convert inputs fp32 -> fp16
// ---------------------------------------------------------------------------
template <int WHICH>
__global__ void round_kernel(const float* __restrict__ src, int n)
{
    __half* dst = (WHICH == 0) ? g_xh : (WHICH == 1) ? g_wqkvh : g_wprojh;
    int stride = gridDim.x * blockDim.x * 8;
    for (int i = (blockIdx.x * blockDim.x + threadIdx.x) * 8; i < n; i += stride) {
        float4 v0 = *(const float4*)(src + i);
        float4 v1 = *(const float4*)(src + i + 4);
        __half2 h0 = __floats2half2_rn(v0.x, v0.y);
        __half2 h1 = __floats2half2_rn(v0.z, v0.w);
        __half2 h2 = __floats2half2_rn(v1.x, v1.y);
        __half2 h3 = __floats2half2_rn(v1.z, v1.w);
        uint4 u;
        u.x = *(uint32_t*)&h0;  u.y = *(uint32_t*)&h1;
        u.z = *(uint32_t*)&h2;  u.w = *(uint32_t*)&h3;
        *(uint4*)(dst + i) = u;
    }
}

// ---------------------------------------------------------------------------
// fp16 GEMM: C[M,N] = A[M,K] * Bw[N,K]^T via m16n8k16 mma (fp32 accum).
// Block 128x128, K-block 64 halfs. 256 thr = 8 warps (2m x 4n), warp 64x32.
// 3-stage cp.async (issue-then-wait2), 1 sync/iter, 2 CTAs/SM.
// smem rows: 64 halfs = 128B = 8 chunks of 16B, chunk col' = c8 ^ (row&7).
// ---------------------------------------------------------------------------
#define BK 64
#define GSTAGES 3
#define STG_B 16384
#define GEMM_SMEM (GSTAGES * 2 * STG_B)   // 98304
#define NKIT (KDIM / BK)                  // 32

template <int MODE>
__global__ __launch_bounds__(256, 2)
void gemm_kernel(const float* __restrict__ cosT,
                 const float* __restrict__ sinT,
                 const float* __restrict__ bias,
                 float* __restrict__ Cout)
{
    extern __shared__ __half smh[];
    const uint32_t sA = smem_u32(smh);
    const uint32_t sB = sA + GSTAGES * STG_B;

    const int tid  = threadIdx.x;
    const int lane = tid & 31;
    const int w    = tid >> 5;
    const int gy   = lane >> 2;
    const int gx   = lane & 3;
    const int wm   = (w >> 2) * 64;
    const int wn   = (w & 3) * 32;
    const long row0 = (long)blockIdx.x * 128;
    const long col0 = (long)blockIdx.y * 128;

    const __half* __restrict__ Ap = (MODE == 0) ? g_xh    : g_attnh;
    const __half* __restrict__ Bp = (MODE == 0) ? g_wqkvh : g_wprojh;

    int lr[4], lc8[4], soff[4];
#pragma unroll
    for (int j = 0; j < 4; j++) {
        int f = tid + j * 256;
        lr[j]  = f >> 3;
        lc8[j] = f & 7;
        soff[j] = lr[j] * 128 + ((lc8[j] ^ (lr[j] & 7)) * 16);
    }

    const int l7 = lane & 7;
    const int ha = (lane >> 4) & 1;
    const int ra = wm + l7 + 8 * ((lane >> 3) & 1);
    const int hb = (lane >> 3) & 1;
    const int rb = wn + l7 + 8 * ((lane >> 4) & 1);

    auto issue = [&](int kb, int slot) {
        if (kb < KDIM) {
            const uint32_t ba = sA + slot * STG_B;
            const uint32_t bb = sB + slot * STG_B;
#pragma unroll
            for (int j = 0; j < 4; j++) {
                CP16(ba + soff[j], Ap + (row0 + lr[j]) * KDIM + kb + lc8[j] * 8);
                CP16(bb + soff[j], Bp + (col0 + lr[j]) * KDIM + kb + lc8[j] * 8);
            }
        }
        CP_COMMIT();
    };

    float acc[4][4][4];
#pragma unroll
    for (int s = 0; s < 4; s++)
#pragma unroll
        for (int t = 0; t < 4; t++)
#pragma unroll
            for (int j = 0; j < 4; j++) acc[s][t][j] = 0.0f;

    issue(0, 0);
    issue(BK, 1);

    for (int it = 0; it < NKIT; it++) {
        issue((it + 2) * BK, (it + 2) % GSTAGES);
        CP_WAIT2();
        __syncthreads();

        const uint32_t Sa = sA + (it % GSTAGES) * STG_B;
        const uint32_t Sb = sB + (it % GSTAGES) * STG_B;
#pragma unroll
        for (int ks = 0; ks < 4; ks++) {
            const int ca = ((2 * ks + ha) ^ l7) * 16;
            const int cb = ((2 * ks + hb) ^ l7) * 16;
            uint32_t af[4][4], bf[4][2];
#pragma unroll
            for (int s = 0; s < 4; s++)
                LDSM4(af[s][0], af[s][1], af[s][2], af[s][3],
                      Sa + (ra + 16 * s) * 128 + ca);
            LDSM4(bf[0][0], bf[0][1], bf[1][0], bf[1][1], Sb + rb * 128 + cb);
            LDSM4(bf[2][0], bf[2][1], bf[3][0], bf[3][1], Sb + (rb + 16) * 128 + cb);
#pragma unroll
            for (int s = 0; s < 4; s++)
#pragma unroll
                for (int t = 0; t < 4; t++)
                    mma16(acc[s][t], af[s], bf[t]);
        }
        __syncthreads();
    }

    // Epilogue. rows: row0+wm+16s+gy+8h; cols: col0+wn+8t+2gx(+1).
    if (MODE == 0) {
        const int sec  = (int)(col0 >> 11);
        const int head = ((int)col0 >> 7) & 15;
        const float qscale = 0.08838834764831845f;
#pragma unroll
        for (int s = 0; s < 4; s++)
#pragma unroll
            for (int t = 0; t < 4; t++) {
                const int d = wn + 8 * t + 2 * gx;
                const int p = d >> 1;
#pragma unroll
                for (int h = 0; h < 2; h++) {
                    long r = row0 + wm + 16 * s + gy + 8 * h;
                    int  b  = (int)(r >> 11);
                    int  tt = (int)r & 2047;
                    float v0 = acc[s][t][2 * h + 0];
                    float v1 = acc[s][t][2 * h + 1];
                    if (sec < 2) {
                        float c  = cosT[tt * 64 + p];
                        float sn = sinT[tt * 64 + p];
                        float e = v0, o = v1;
                        v0 = e * c - o * sn;
                        v1 = e * sn + o * c;
                        if (sec == 0) { v0 *= qscale; v1 *= qscale; }
                    }
                    long bh = (long)b * NH + head;
                    if (sec == 2) {
                        g_Vth[(bh * HD + d)     * TT + tt] = __float2half_rn(v0);
                        g_Vth[(bh * HD + d + 1) * TT + tt] = __float2half_rn(v1);
                    } else {
                        __half* dst = (sec == 0) ? g_Qh : g_Kh;
                        *(__half2*)&dst[(bh * TT + tt) * HD + d] =
                            __floats2half2_rn(v0, v1);
                    }
                }
            }
    } else {
#pragma unroll
        for (int t = 0; t < 4; t++) {
            const long n = col0 + wn + 8 * t + 2 * gx;
            float2 bv = *(const float2*)&bias[n];
#pragma unroll
            for (int s = 0; s < 4; s++)
#pragma unroll
                for (int h = 0; h < 2; h++) {
                    long r = row0 + wm + 16 * s + gy + 8 * h;
                    *(float2*)&Cout[r * HID + n] =
                        make_float2(acc[s][t][2 * h] + bv.x, acc[s][t][2 * h + 1] + bv.y);
                }
        }
    }
}

// ---------------------------------------------------------------------------
// fp16 flash attention. One block per (bh, 128-q tile). KV tiles of 64.
// 8 warps x 16 q rows. Q frags in regs. 3-stage cp.async (issue-then-wait2).
// Softmax: exp via ex2.approx.f16x2; row-sum l via mma with all-ones B;
// O rescale only when the running max changes (warp-uniform branch).
// ---------------------------------------------------------------------------
#define QT  128
#define KVT 64
#define KSTG_B 16384
#define ATTN_SMEM (3 * KSTG_B + 3 * KSTG_B + 16384)   // 114688
#define NIT (TT / KVT)                                // 32
#define L2E 1.4426950408889634f

__global__ __launch_bounds__(256, 1)
void attn_kernel()
{
    extern __shared__ __half smh[];
    __half* Kst = smh;                    // 3 * 64*128
    __half* Vst = Kst + 3 * 8192;         // 3 * 128*64
    __half* Ps  = Vst + 3 * 8192;         // 128*64

    const int tid  = threadIdx.x;
    const int lane = tid & 31;
    const int w    = tid >> 5;
    const int gy   = lane >> 2;
    const int gx   = lane & 3;
    const int bh   = blockIdx.y;
    const int q0   = blockIdx.x * QT;
    const int qw   = w * 16;

    const __half* __restrict__ Qg = g_Qh  + (long)bh * TT * HD;
    const __half* __restrict__ Kg = g_Kh  + (long)bh * TT * HD;
    const __half* __restrict__ Vg = g_Vth + (long)bh * HD * TT;

    const uint32_t sK = smem_u32(Kst);
    const uint32_t sV = smem_u32(Vst);
    const uint32_t sP = smem_u32(Ps);

    const int l7  = lane & 7;
    const int hb  = (lane >> 3) & 1;
    const int hp  = (lane >> 4) & 1;
    const int rkv = 8 * ((lane >> 4) & 1) + l7;
    const int rowp = qw + l7 + 8 * ((lane >> 3) & 1);

    // ---- Stage Q in smem (Kst area), pull m16n8k16 A-frags to registers ----
    uint32_t q[8][4];
    {
        __half* Qtmp = Kst;
#pragma unroll
        for (int i = 0; i < 8; i++) {
            int f = tid + i * 256;
            int r = f >> 4, c8 = f & 15;
            int cs = (c8 & 8) | ((c8 & 7) ^ (r & 7));
            *(uint4*)&Qtmp[r * 128 + cs * 8] =
                *(const uint4*)&Qg[(long)(q0 + r) * HD + c8 * 8];
        }
        __syncthreads();
        const uint32_t qbase = smem_u32(Qtmp) + rowp * 256;
#pragma unroll
        for (int ks = 0; ks < 8; ks++) {
            const int c8 = 2 * ks + hp;
            const int cs = (c8 & 8) | ((c8 & 7) ^ l7);
            LDSM4(q[ks][0], q[ks][1], q[ks][2], q[ks][3], qbase + cs * 16);
        }
        __syncthreads();
    }

    auto issueKV = [&](int kv0, int slot) {
        if (kv0 < TT) {
#pragma unroll
            for (int i = 0; i < 4; i++) {
                int f = tid + i * 256;
                int r = f >> 4, c8 = f & 15;
                int cs = (c8 & 8) | ((c8 & 7) ^ (r & 7));
                CP16(sK + slot * KSTG_B + r * 256 + cs * 16,
                     Kg + (long)(kv0 + r) * HD + c8 * 8);
            }
#pragma unroll
            for (int i = 0; i < 4; i++) {
                int f = tid + i * 256;
                int d = f >> 3, c8 = f & 7;
                CP16(sV + slot * KSTG_B + d * 128 + ((c8 ^ (d & 7)) * 16),
                     Vg + (long)d * TT + kv0 + c8 * 8);
            }
        }
        CP_COMMIT();
    };

    float o[16][4];
#pragma unroll
    for (int dt = 0; dt < 16; dt++)
#pragma unroll
        for (int j = 0; j < 4; j++) o[dt][j] = 0.0f;
    float lacc[4] = {0.0f, 0.0f, 0.0f, 0.0f};     // rows (qw+gy, qw+gy+8) sums
    float m0 = -3.0e38f, m1 = -3.0e38f;

    const uint32_t bones[2] = {0x3C003C00u, 0x3C003C00u};   // 1.0h x4

    issueKV(0, 0);
    issueKV(KVT, 1);

    for (int i = 0; i < NIT; i++) {
        issueKV((i + 2) * KVT, (i + 2) % 3);
        CP_WAIT2();
        __syncthreads();

        const uint32_t Kb = sK + (i % 3) * KSTG_B;
        const uint32_t Vb = sV + (i % 3) * KSTG_B;

        // S = Q.K^T : warp 16 x 64, k = 128 (8 k-steps)
        float s4[8][4];
#pragma unroll
        for (int t = 0; t < 8; t++)
#pragma unroll
            for (int j = 0; j < 4; j++) s4[t][j] = 0.0f;

#pragma unroll
        for (int ks = 0; ks < 8; ks++) {
            const int c8 = 2 * ks + hb;
            const int cs = ((c8 & 8) | ((c8 & 7) ^ l7)) * 16;
#pragma unroll
            for (int tp = 0; tp < 4; tp++) {
                uint32_t bf[2][2];
                LDSM4(bf[0][0], bf[0][1], bf[1][0], bf[1][1],
                      Kb + (rkv + 16 * tp) * 256 + cs);
                mma16(s4[2 * tp],     q[ks], bf[0]);
                mma16(s4[2 * tp + 1], q[ks], bf[1]);
            }
        }

        // row max (rows qw+gy, qw+gy+8) over 16-lane groups
        float mx0 = -3.0e38f, mx1 = -3.0e38f;
#pragma unroll
        for (int t = 0; t < 8; t++) {
            mx0 = fmaxf(mx0, fmaxf(s4[t][0], s4[t][1]));
            mx1 = fmaxf(mx1, fmaxf(s4[t][2], s4[t][3]));
        }
        mx0 = fmaxf(mx0, __shfl_xor_sync(0xffffffffu, mx0, 1));
        mx0 = fmaxf(mx0, __shfl_xor_sync(0xffffffffu, mx0, 2));
        mx1 = fmaxf(mx1, __shfl_xor_sync(0xffffffffu, mx1, 1));
        mx1 = fmaxf(mx1, __shfl_xor_sync(0xffffffffu, mx1, 2));

        float mn0 = fmaxf(m0, mx0), mn1 = fmaxf(m1, mx1);
        float al0 = __expf(m0 - mn0), al1 = __expf(m1 - mn1);
        m0 = mn0;  m1 = mn1;

        // rescale O and l only when a max actually moved (warp-uniform)
        if (__any_sync(0xffffffffu, (al0 < 1.0f) || (al1 < 1.0f))) {
#pragma unroll
            for (int dt = 0; dt < 16; dt++) {
                o[dt][0] *= al0; o[dt][1] *= al0;
                o[dt][2] *= al1; o[dt][3] *= al1;
            }
            lacc[0] *= al0;  lacc[2] *= al1;
        }

        // P = 2^((s-m) * log2e) via ex2.approx.f16x2; store directly to smem
        const float nb0 = mn0 * L2E, nb1 = mn1 * L2E;
#pragma unroll
        for (int t = 0; t < 8; t++) {
            float t0 = fmaf(s4[t][0], L2E, -nb0);
            float t1 = fmaf(s4[t][1], L2E, -nb0);
            float t2 = fmaf(s4[t][2], L2E, -nb1);
            float t3 = fmaf(s4[t][3], L2E, -nb1);
            __half2 h01 = __floats2half2_rn(t0, t1);
            __half2 h23 = __floats2half2_rn(t2, t3);
            uint32_t p01, p23;
            asm("ex2.approx.f16x2 %0, %1;" : "=r"(p01) : "r"(*(uint32_t*)&h01));
            asm("ex2.approx.f16x2 %0, %1;" : "=r"(p23) : "r"(*(uint32_t*)&h23));
            int cs = t ^ gy;
            *(uint32_t*)&Ps[(qw + gy)     * 64 + cs * 8 + gx * 2] = p01;
            *(uint32_t*)&Ps[(qw + gy + 8) * 64 + cs * 8 + gx * 2] = p23;
        }
        __syncwarp();

        // O += P.V (and l += P.1) : warp 16 x 128, k = 64 (4 k-steps)
#pragma unroll
        for (int ks = 0; ks < 4; ks++) {
            uint32_t a[4];
            LDSM4(a[0], a[1], a[2], a[3],
                  sP + rowp * 128 + (((2 * ks + hp) ^ l7) * 16));
            mma16(lacc, a, bones);          // row-sum of P via tensor core
            const int cs = ((2 * ks + hb) ^ l7) * 16;
#pragma unroll
            for (int tp = 0; tp < 8; tp++) {
                uint32_t bf[2][2];
                LDSM4(bf[0][0], bf[0][1], bf[1][0], bf[1][1],
                      Vb + (rkv + 16 * tp) * 128 + cs);
                mma16(o[2 * tp],     a, bf[0]);
                mma16(o[2 * tp + 1], a, bf[1]);
            }
        }
    }

    // finalize: /l, fp16 (input of out-proj), write [B,T,NH*HD]
    const int b = bh >> 4, h = bh & 15;
    const float inv0 = 1.0f / lacc[0], inv1 = 1.0f / lacc[2];
    const long t0 = q0 + qw + gy;
#pragma unroll
    for (int dt = 0; dt < 16; dt++) {
        int d = 8 * dt + 2 * gx;
        long base0 = ((long)b * TT + t0)     * HID + h * HD + d;
        long base1 = ((long)b * TT + t0 + 8) * HID + h * HD + d;
        *(__half2*)&g_attnh[base0] = __floats2half2_rn(o[dt][0] * inv0, o[dt][1] * inv0);
        *(__half2*)&g_attnh[base1] = __floats2half2_rn(o[dt][2] * inv1, o[dt][3] * inv1);
    }
}

// ---------------------------------------------------------------------------
extern "C" void kernel_launch(void* const* d_in, const int* in_sizes, int n_in,
                              void* d_out, int out_size)
{
    const float* x      = (const float*)d_in[0];
    const float* w_qkv  = (const float*)d_in[1];
    const float* w_proj = (const float*)d_in[2];
    const float* b_proj = (const float*)d_in[3];
    const float* cosT   = (const float*)d_in[4];
    const float* sinT   = (const float*)d_in[5];
    float* out = (float*)d_out;

    cudaFuncSetAttribute(gemm_kernel<0>,
                         cudaFuncAttributeMaxDynamicSharedMemorySize, GEMM_SMEM);
    cudaFuncSetAttribute(gemm_kernel<1>,
                         cudaFuncAttributeMaxDynamicSharedMemorySize, GEMM_SMEM);
    cudaFuncSetAttribute(attn_kernel,
                         cudaFuncAttributeMaxDynamicSharedMemorySize, ATTN_SMEM);

    // 0) convert inputs to fp16
    round_kernel<0><<<1024, 256>>>(x,      MTOT * KDIM);
    round_kernel<1><<<1024, 256>>>(w_qkv,  3 * HID * KDIM);
    round_kernel<2><<<1024, 256>>>(w_proj, HID * KDIM);

    // 1) QKV proj (fp16 mma) + RoPE + scatter (V transposed)
    gemm_kernel<0><<<dim3(MTOT / 128, (3 * HID) / 128), 256, GEMM_SMEM>>>(
        cosT, sinT, nullptr, nullptr);

    // 2) attention (fp16 mma)
    attn_kernel<<<dim3(TT / QT, BB * NH), 256, ATTN_SMEM>>>();

    // 3) out proj (fp16 mma) + bias
    gemm_kernel<1><<<dim3(MTOT / 128, HID / 128), 256, GEMM_SMEM>>>(
        nullptr, nullptr, b_proj, out);
}